// round 15
// baseline (speedup 1.0000x reference)
#include <cuda_runtime.h>
#include <cuda_pipeline.h>
#include <math.h>

#define BB    64
#define DD    1024
#define LL    2048
#define DH    512
#define SPLIT 16
#define LC    (LL / SPLIT)   // 128 rows per CTA
#define NPAIR (LC / 16)      // 8 pairs per warp (8 warps, 2 rows each)

// dynamic smem (floats): ring[8][2][2][512] | sq 1024 | sacc 1024 | slog 256 | smx 16 | ssm 16
#define RING_F (8 * 2 * 2 * 512)
#define SMEM_F (RING_F + 1024 + 1024 + 256 + 16 + 16)
#define SMEM_BYTES (SMEM_F * 4)

typedef unsigned long long u64;

// ---------------- f32x2 packed helpers (sm_103a) ----------------
__device__ __forceinline__ u64 pack2(float lo, float hi) {
    u64 r; asm("mov.b64 %0, {%1, %2};" : "=l"(r) : "f"(lo), "f"(hi)); return r;
}
__device__ __forceinline__ void unpack2(u64 v, float& lo, float& hi) {
    asm("mov.b64 {%0, %1}, %2;" : "=f"(lo), "=f"(hi) : "l"(v));
}
__device__ __forceinline__ u64 fma2(u64 a, u64 b, u64 c) {
    u64 d; asm("fma.rn.f32x2 %0, %1, %2, %3;" : "=l"(d) : "l"(a), "l"(b), "l"(c)); return d;
}
__device__ __forceinline__ u64 mul2(u64 a, u64 b) {
    u64 d; asm("mul.rn.f32x2 %0, %1, %2;" : "=l"(d) : "l"(a), "l"(b)); return d;
}

// ---------------- device scratch (16B-aligned) ----------------
__device__ __align__(16) float g_target[BB * DD];
__device__ __align__(16) float g_acc5[BB * DD];
__device__ __align__(16) float g_wctx[BB * DD];
__device__ __align__(16) float g_pm[BB * 2 * SPLIT];
__device__ __align__(16) float g_ps[BB * 2 * SPLIT];
__device__ __align__(16) float g_pacc[BB * 2 * SPLIT * DH];
__device__ __align__(16) unsigned g_tile_ctr[16];

// ---------------- idx 0: zero accumulators + tile counters (PDL top-sync) ---
__global__ void prep_kernel() {
    cudaGridDependencySynchronize();   // prev replay's final_k reads g_acc5/out
    int i = blockIdx.x * 256 + threadIdx.x;
    if (i < BB * DD) { g_target[i] = 0.f; g_acc5[i] = 0.f; }
    if (i < 16) g_tile_ctr[i] = 0u;
}

// ---------------- split-K NT GEMM body; optional PDL sync before epilogue ----
__device__ __forceinline__ void gemm_body(const float* __restrict__ A, int lda,
                                          const float* __restrict__ B, int ldb,
                                          float* __restrict__ C, int kchunk,
                                          int n0, int k0, bool pdl_epi_sync) {
    __shared__ __align__(16) float As[16][68];
    __shared__ __align__(16) float Bs[16][68];
    int tid  = threadIdx.x;
    int tx   = tid & 15, ty = tid >> 4;
    int lrow = tid >> 2, lcol = (tid & 3) << 2;

    const float* Ap = A + (size_t)lrow * lda + lcol;
    const float* Bp = B + (size_t)(n0 + lrow) * ldb + lcol;

    float acc[4][4];
#pragma unroll
    for (int i = 0; i < 4; i++)
#pragma unroll
        for (int j = 0; j < 4; j++) acc[i][j] = 0.f;

    for (int kk = k0; kk < k0 + kchunk; kk += 16) {
        float4 a = *(const float4*)(Ap + kk);
        float4 b = *(const float4*)(Bp + kk);
        __syncthreads();
        As[lcol + 0][lrow] = a.x; As[lcol + 1][lrow] = a.y;
        As[lcol + 2][lrow] = a.z; As[lcol + 3][lrow] = a.w;
        Bs[lcol + 0][lrow] = b.x; Bs[lcol + 1][lrow] = b.y;
        Bs[lcol + 2][lrow] = b.z; Bs[lcol + 3][lrow] = b.w;
        __syncthreads();
#pragma unroll
        for (int k = 0; k < 16; k++) {
            float4 av = *(const float4*)&As[k][ty << 2];
            float4 bv = *(const float4*)&Bs[k][tx << 2];
            float aa[4] = {av.x, av.y, av.z, av.w};
            float bb[4] = {bv.x, bv.y, bv.z, bv.w};
#pragma unroll
            for (int i = 0; i < 4; i++)
#pragma unroll
                for (int j = 0; j < 4; j++)
                    acc[i][j] = fmaf(aa[i], bb[j], acc[i][j]);
        }
    }
    if (pdl_epi_sync) cudaGridDependencySynchronize();  // C zeroed by prep
    int row = ty << 2, col = n0 + (tx << 2);
#pragma unroll
    for (int i = 0; i < 4; i++)
#pragma unroll
        for (int j = 0; j < 4; j++)
            atomicAdd(&C[(size_t)(row + i) * DD + col + j], acc[i][j]);
}

// ---------------- idx 1: both input GEMMs (PDL: main loop overlaps prep) ----
__global__ __launch_bounds__(256) void gemm_dual(const float* __restrict__ inp,
                                                 const float* __restrict__ Win,
                                                 const float* __restrict__ Wout) {
    if (blockIdx.z == 0)
        gemm_body(inp, DD, Win, DD, g_target, DD / 8,
                  blockIdx.x * 64, blockIdx.y * (DD / 8), true);
    else
        gemm_body(inp, DD, Wout + DD, 2 * DD, g_acc5, DD / 8,
                  blockIdx.x * 64, blockIdx.y * (DD / 8), true);
}

// ---------------- idx 2: fused attention, f32x2 packed math + PDL prologue --
__global__ __launch_bounds__(256, 3) void attn_pass(const float* __restrict__ ctx,
                                                    float* __restrict__ attn0,
                                                    float* __restrict__ attn1) {
    extern __shared__ __align__(16) float sm[];
    float* ring = sm;                 // [w][stage][row][512]
    float* sqm  = sm + RING_F;        // [k][j][lane][4]
    float* sacc = sqm + 1024;         // [2][512]
    float* slog = sacc + 1024;        // [2][128]
    float* smx  = slog + 256;         // [2][8]
    float* ssm  = smx + 16;           // [2][8]

    const int b = blockIdx.y, sp = blockIdx.x;
    const int tid = threadIdx.x, lane = tid & 31, w = tid >> 5;

    const float* cbase = ctx + ((size_t)b * LL + (size_t)sp * LC) * DH;

    auto pf = [&](int p, int s) {
        const float* src = cbase + (size_t)(16 * p + 2 * w) * DH + lane * 4;
        float* dst = ring + (size_t)((w * 2 + s) * 2) * 512 + lane * 4;
#pragma unroll
        for (int i = 0; i < 8; i++)
            __pipeline_memcpy_async(dst + i * 128, src + i * 128, 16);
    };

    // PDL prologue: context prefetch + sacc zero before g_target dependence
    pf(0, 0); __pipeline_commit();
    for (int i = tid; i < 2 * DH; i += 256) sacc[i] = 0.f;

    cudaGridDependencySynchronize();   // g_target now valid

    {   // sq[k][j][l][t] = target[b, (l+32j)*8 + 2t + k]
        int k = tid >> 7, j = (tid >> 5) & 3, l = tid & 31;
        const float* g = g_target + (size_t)b * DD + (size_t)(l + 32 * j) * 8 + k;
        float4 v; v.x = g[0]; v.y = g[2]; v.z = g[4]; v.w = g[6];
        *(float4*)&sqm[((k * 4 + j) * 32 + l) * 4] = v;
    }
    __syncthreads();

    u64 a0p[8], a1p[8];                // packed accumulators (16 floats each)
#pragma unroll
    for (int i = 0; i < 8; i++) { a0p[i] = 0ull; a1p[i] = 0ull; }
    float m0 = -1e30f, m1 = -1e30f, s0 = 0.f, s1 = 0.f;

#pragma unroll
    for (int p = 0; p < NPAIR; p++) {
        const int st = p & 1;
        if (p + 1 < NPAIR) pf(p + 1, st ^ 1);
        __pipeline_commit();
        __pipeline_wait_prior(1);
        __syncwarp();

        const float* rA = ring + (size_t)((w * 2 + st) * 2) * 512;
        const float* rB = rA + 512;

        // packed dot products: 32 FFMA2 instead of 64 FFMA
        u64 pA0 = 0ull, pA1 = 0ull, pB0 = 0ull, pB1 = 0ull;
#pragma unroll
        for (int j = 0; j < 4; j++) {
            float4 q0v = *(const float4*)&sqm[((0 * 4 + j) * 32 + lane) * 4];
            float4 q1v = *(const float4*)&sqm[((1 * 4 + j) * 32 + lane) * 4];
            float4 va  = *(const float4*)&rA[(lane + 32 * j) * 4];
            float4 vb  = *(const float4*)&rB[(lane + 32 * j) * 4];
            u64 q0a = pack2(q0v.x, q0v.y), q0b = pack2(q0v.z, q0v.w);
            u64 q1a = pack2(q1v.x, q1v.y), q1b = pack2(q1v.z, q1v.w);
            u64 vaa = pack2(va.x, va.y),   vab = pack2(va.z, va.w);
            u64 vba = pack2(vb.x, vb.y),   vbb = pack2(vb.z, vb.w);
            pA0 = fma2(vaa, q0a, pA0); pA0 = fma2(vab, q0b, pA0);
            pA1 = fma2(vaa, q1a, pA1); pA1 = fma2(vab, q1b, pA1);
            pB0 = fma2(vba, q0a, pB0); pB0 = fma2(vbb, q0b, pB0);
            pB1 = fma2(vba, q1a, pB1); pB1 = fma2(vbb, q1b, pB1);
        }
        float xa, xb, dA0, dA1, dB0, dB1;
        unpack2(pA0, xa, xb); dA0 = xa + xb;
        unpack2(pA1, xa, xb); dA1 = xa + xb;
        unpack2(pB0, xa, xb); dB0 = xa + xb;
        unpack2(pB1, xa, xb); dB1 = xa + xb;
#pragma unroll
        for (int o = 16; o; o >>= 1) {
            dA0 += __shfl_xor_sync(0xffffffffu, dA0, o);
            dA1 += __shfl_xor_sync(0xffffffffu, dA1, o);
            dB0 += __shfl_xor_sync(0xffffffffu, dB0, o);
            dB1 += __shfl_xor_sync(0xffffffffu, dB1, o);
        }
        int r = 16 * p + 2 * w;
        if (lane == 0) {
            slog[0 * 128 + r] = dA0; slog[0 * 128 + r + 1] = dB0;
            slog[1 * 128 + r] = dA1; slog[1 * 128 + r + 1] = dB1;
        }
        // pairwise online softmax (proven math)
        float n0 = fmaxf(m0, fmaxf(dA0, dB0));
        float n1 = fmaxf(m1, fmaxf(dA1, dB1));
        float r0 = __expf(m0 - n0), r1 = __expf(m1 - n1);
        float eA0 = __expf(dA0 - n0), eB0 = __expf(dB0 - n0);
        float eA1 = __expf(dA1 - n1), eB1 = __expf(dB1 - n1);
        s0 = s0 * r0 + eA0 + eB0; m0 = n0;
        s1 = s1 * r1 + eA1 + eB1; m1 = n1;
        if (r0 != 1.f || r1 != 1.f) {
            u64 r0p = pack2(r0, r0), r1p = pack2(r1, r1);
#pragma unroll
            for (int i = 0; i < 8; i++) {
                a0p[i] = mul2(a0p[i], r0p);
                a1p[i] = mul2(a1p[i], r1p);
            }
        }
        // packed accumulate: 32 FFMA2 instead of 64 FFMA
        u64 eA0p = pack2(eA0, eA0), eB0p = pack2(eB0, eB0);
        u64 eA1p = pack2(eA1, eA1), eB1p = pack2(eB1, eB1);
#pragma unroll
        for (int j = 0; j < 4; j++) {
            float4 va = *(const float4*)&rA[(lane + 32 * j) * 4];
            float4 vb = *(const float4*)&rB[(lane + 32 * j) * 4];
            u64 vaa = pack2(va.x, va.y), vab = pack2(va.z, va.w);
            u64 vba = pack2(vb.x, vb.y), vbb = pack2(vb.z, vb.w);
            a0p[2 * j + 0] = fma2(eB0p, vba, fma2(eA0p, vaa, a0p[2 * j + 0]));
            a0p[2 * j + 1] = fma2(eB0p, vbb, fma2(eA0p, vab, a0p[2 * j + 1]));
            a1p[2 * j + 0] = fma2(eB1p, vba, fma2(eA1p, vaa, a1p[2 * j + 0]));
            a1p[2 * j + 1] = fma2(eB1p, vbb, fma2(eA1p, vab, a1p[2 * j + 1]));
        }
    }

    if (lane == 0) {
        smx[0 * 8 + w] = m0; smx[1 * 8 + w] = m1;
        ssm[0 * 8 + w] = s0; ssm[1 * 8 + w] = s1;
    }
    __syncthreads();

    {   // bulk coalesced store of raw logits (normalized in combine2)
        float* a0s = attn0 + (size_t)b * LL + sp * LC;
        float* a1s = attn1 + (size_t)b * LL + sp * LC;
        for (int i = tid; i < LC; i += 256) {
            a0s[i] = slog[0 * 128 + i];
            a1s[i] = slog[1 * 128 + i];
        }
    }

    float M0 = -1e30f, M1 = -1e30f;
#pragma unroll
    for (int ww = 0; ww < 8; ww++) {
        M0 = fmaxf(M0, smx[0 * 8 + ww]);
        M1 = fmaxf(M1, smx[1 * 8 + ww]);
    }
    float f0 = __expf(m0 - M0);
    float f1 = __expf(m1 - M1);
#pragma unroll
    for (int j = 0; j < 4; j++)
#pragma unroll
        for (int t = 0; t < 2; t++) {
            float x, y;
            int d = (lane + 32 * j) * 4 + 2 * t;
            unpack2(a0p[2 * j + t], x, y);
            atomicAdd(&sacc[d],     x * f0);
            atomicAdd(&sacc[d + 1], y * f0);
            unpack2(a1p[2 * j + t], x, y);
            atomicAdd(&sacc[DH + d],     x * f1);
            atomicAdd(&sacc[DH + d + 1], y * f1);
        }
    __syncthreads();

    int idx0 = (b * 2 + 0) * SPLIT + sp;
    int idx1 = (b * 2 + 1) * SPLIT + sp;
    if (tid == 0) {
        float S0 = 0.f, S1 = 0.f;
#pragma unroll
        for (int ww = 0; ww < 8; ww++) {
            S0 += ssm[0 * 8 + ww] * __expf(smx[0 * 8 + ww] - M0);
            S1 += ssm[1 * 8 + ww] * __expf(smx[1 * 8 + ww] - M1);
        }
        g_pm[idx0] = M0; g_ps[idx0] = S0;
        g_pm[idx1] = M1; g_ps[idx1] = S1;
    }
    for (int i = tid; i < DH; i += 256) {
        g_pacc[(size_t)idx0 * DH + i] = sacc[i];
        g_pacc[(size_t)idx1 * DH + i] = sacc[DH + i];
    }
}

// ---------------- idx 3: combine + normalize logits (PDL top-sync) ----------
__global__ __launch_bounds__(256) void combine2(float* __restrict__ out) {
    cudaGridDependencySynchronize();   // g_pm/g_ps/g_pacc + raw logits from attn
    int bk = blockIdx.x >> 1;
    int half = blockIdx.x & 1;
    int d  = half * 256 + threadIdx.x;

    float pm[SPLIT], wv[SPLIT];
#pragma unroll
    for (int i = 0; i < SPLIT; i++) pm[i] = g_pm[bk * SPLIT + i];
    float M = pm[0];
#pragma unroll
    for (int i = 1; i < SPLIT; i++) M = fmaxf(M, pm[i]);
    float S = 0.f;
#pragma unroll
    for (int i = 0; i < SPLIT; i++) {
        wv[i] = __expf(pm[i] - M);
        S += g_ps[bk * SPLIT + i] * wv[i];
    }
    float inv = 1.0f / S;

    const float* pa = g_pacc + (size_t)bk * SPLIT * DH + d;
    float acc = 0.f;
#pragma unroll
    for (int i = 0; i < SPLIT; i++) acc += pa[(size_t)i * DH] * wv[i];
    int b = bk >> 1, k = bk & 1;
    g_wctx[(size_t)b * DD + k * DH + d] = acc * inv;

    // normalize this (b,k)'s logits: 1024 contiguous floats per CTA
    float* ap = out + BB * DD + (size_t)k * BB * LL + (size_t)b * LL
              + half * 1024 + threadIdx.x * 4;
    float4 v = *(float4*)ap;
    v.x = __expf(v.x - M) * inv;
    v.y = __expf(v.y - M) * inv;
    v.z = __expf(v.z - M) * inv;
    v.w = __expf(v.w - M) * inv;
    *(float4*)ap = v;
}

// ---------------- idx 4: pure output GEMM + tanh ticket (PDL top-sync) ------
__global__ __launch_bounds__(256) void final_k(const float* __restrict__ Wout,
                                               float* __restrict__ out) {
    cudaGridDependencySynchronize();   // g_wctx from combine2
    int tile = blockIdx.x >> 3, split = blockIdx.x & 7;
    gemm_body(g_wctx, DD, Wout, 2 * DD, g_acc5, DD / 8,
              tile * 64, split * (DD / 8), false);
    __threadfence();
    __shared__ unsigned s_old;
    __syncthreads();
    if (threadIdx.x == 0) s_old = atomicAdd(&g_tile_ctr[tile], 1u);
    __syncthreads();
    if (s_old == 7u) {
        __threadfence();
        int n0 = tile * 64;
        for (int i = threadIdx.x; i < 64 * 64; i += 256) {
            int r = i >> 6, c = i & 63;
            out[(size_t)r * DD + n0 + c] = tanhf(g_acc5[(size_t)r * DD + n0 + c]);
        }
    }
}

// ---------------- PDL launch helper ----------------
template <typename F, typename... Args>
static inline void launch_pdl(F kern, dim3 grid, dim3 block, size_t shm, Args... args) {
    cudaLaunchConfig_t cfg = {};
    cfg.gridDim = grid; cfg.blockDim = block;
    cfg.dynamicSmemBytes = shm; cfg.stream = 0;
    cudaLaunchAttribute attr[1];
    attr[0].id = cudaLaunchAttributeProgrammaticStreamSerialization;
    attr[0].val.programmaticStreamSerializationAllowed = 1;
    cfg.attrs = attr; cfg.numAttrs = 1;
    cudaLaunchKernelEx(&cfg, kern, args...);
}

// ---------------- launcher: 5 kernels, all PDL-chained ----------------
extern "C" void kernel_launch(void* const* d_in, const int* in_sizes, int n_in,
                              void* d_out, int out_size) {
    const float* input   = (const float*)d_in[0]; // [64,1024]
    const float* context = (const float*)d_in[1]; // [64,2048,512]
    const float* W_in    = (const float*)d_in[2]; // [1024,1024]
    const float* W_out   = (const float*)d_in[3]; // [1024,2048]
    float* out = (float*)d_out;                   // [ctxOut | attn0 | attn1]
    float* attn0 = out + BB * DD;
    float* attn1 = attn0 + BB * LL;

    static int inited = 0;
    if (!inited) {
        cudaFuncSetAttribute(attn_pass, cudaFuncAttributeMaxDynamicSharedMemorySize, SMEM_BYTES);
        inited = 1;
    }

    launch_pdl(prep_kernel, dim3(256), dim3(256), 0);
    launch_pdl(gemm_dual, dim3(16, 8, 2), dim3(256), 0, input, W_in, W_out);
    launch_pdl(attn_pass, dim3(SPLIT, BB), dim3(256), (size_t)SMEM_BYTES,
               (const float*)context, attn0, attn1);
    launch_pdl(combine2, dim3(256), dim3(256), 0, out);
    launch_pdl(final_k, dim3(128), dim3(256), 0, (const float*)W_out, out);
}

// round 16
// speedup vs baseline: 1.1447x; 1.1447x over previous
#include <cuda_runtime.h>
#include <cuda_pipeline.h>
#include <math.h>

#define BB    64
#define DD    1024
#define LL    2048
#define DH    512
#define SPLIT 16
#define LC    (LL / SPLIT)   // 128 rows per CTA
#define NPAIR (LC / 16)      // 8 pairs per warp (8 warps, 2 rows each)

// dynamic smem (floats): ring[8][2][2][512] | sq 1024 | sacc 1024 | slog 256 | smx 16 | ssm 16
#define RING_F (8 * 2 * 2 * 512)
#define SMEM_F (RING_F + 1024 + 1024 + 256 + 16 + 16)
#define SMEM_BYTES (SMEM_F * 4)

// ---------------- device scratch (16B-aligned) ----------------
__device__ __align__(16) float g_target[BB * DD];
__device__ __align__(16) float g_acc5[BB * DD];
__device__ __align__(16) float g_wctx[BB * DD];
__device__ __align__(16) float g_pm[BB * 2 * SPLIT];
__device__ __align__(16) float g_ps[BB * 2 * SPLIT];
__device__ __align__(16) float g_pacc[BB * 2 * SPLIT * DH];
__device__ __align__(16) unsigned g_tile_ctr[16];

// ---------------- idx 0: zero accumulators + tile counters (PDL top-sync) ---
__global__ void prep_kernel() {
    cudaGridDependencySynchronize();
    int i = blockIdx.x * 256 + threadIdx.x;
    if (i < BB * DD) { g_target[i] = 0.f; g_acc5[i] = 0.f; }
    if (i < 16) g_tile_ctr[i] = 0u;
}

// ---------------- split-K NT GEMM body; optional PDL sync before epilogue ----
__device__ __forceinline__ void gemm_body(const float* __restrict__ A, int lda,
                                          const float* __restrict__ B, int ldb,
                                          float* __restrict__ C, int kchunk,
                                          int n0, int k0, bool pdl_epi_sync) {
    __shared__ __align__(16) float As[16][68];
    __shared__ __align__(16) float Bs[16][68];
    int tid  = threadIdx.x;
    int tx   = tid & 15, ty = tid >> 4;
    int lrow = tid >> 2, lcol = (tid & 3) << 2;

    const float* Ap = A + (size_t)lrow * lda + lcol;
    const float* Bp = B + (size_t)(n0 + lrow) * ldb + lcol;

    float acc[4][4];
#pragma unroll
    for (int i = 0; i < 4; i++)
#pragma unroll
        for (int j = 0; j < 4; j++) acc[i][j] = 0.f;

    for (int kk = k0; kk < k0 + kchunk; kk += 16) {
        float4 a = *(const float4*)(Ap + kk);
        float4 b = *(const float4*)(Bp + kk);
        __syncthreads();
        As[lcol + 0][lrow] = a.x; As[lcol + 1][lrow] = a.y;
        As[lcol + 2][lrow] = a.z; As[lcol + 3][lrow] = a.w;
        Bs[lcol + 0][lrow] = b.x; Bs[lcol + 1][lrow] = b.y;
        Bs[lcol + 2][lrow] = b.z; Bs[lcol + 3][lrow] = b.w;
        __syncthreads();
#pragma unroll
        for (int k = 0; k < 16; k++) {
            float4 av = *(const float4*)&As[k][ty << 2];
            float4 bv = *(const float4*)&Bs[k][tx << 2];
            float aa[4] = {av.x, av.y, av.z, av.w};
            float bb[4] = {bv.x, bv.y, bv.z, bv.w};
#pragma unroll
            for (int i = 0; i < 4; i++)
#pragma unroll
                for (int j = 0; j < 4; j++)
                    acc[i][j] = fmaf(aa[i], bb[j], acc[i][j]);
        }
    }
    if (pdl_epi_sync) cudaGridDependencySynchronize();  // C zeroed by prep
    int row = ty << 2, col = n0 + (tx << 2);
#pragma unroll
    for (int i = 0; i < 4; i++)
#pragma unroll
        for (int j = 0; j < 4; j++)
            atomicAdd(&C[(size_t)(row + i) * DD + col + j], acc[i][j]);
}

// ---------------- idx 1: both input GEMMs (PDL: main loop overlaps prep) ----
__global__ __launch_bounds__(256) void gemm_dual(const float* __restrict__ inp,
                                                 const float* __restrict__ Win,
                                                 const float* __restrict__ Wout) {
    if (blockIdx.z == 0)
        gemm_body(inp, DD, Win, DD, g_target, DD / 8,
                  blockIdx.x * 64, blockIdx.y * (DD / 8), true);
    else
        gemm_body(inp, DD, Wout + DD, 2 * DD, g_acc5, DD / 8,
                  blockIdx.x * 64, blockIdx.y * (DD / 8), true);
}

// ---------------- idx 2: fused attention (R14-proven scalar body + PDL) -----
__global__ __launch_bounds__(256, 3) void attn_pass(const float* __restrict__ ctx,
                                                    float* __restrict__ attn0,
                                                    float* __restrict__ attn1) {
    extern __shared__ __align__(16) float sm[];
    float* ring = sm;                 // [w][stage][row][512]
    float* sqm  = sm + RING_F;        // [k][j][lane][4]
    float* sacc = sqm + 1024;         // [2][512]
    float* slog = sacc + 1024;        // [2][128]
    float* smx  = slog + 256;         // [2][8]
    float* ssm  = smx + 16;           // [2][8]

    const int b = blockIdx.y, sp = blockIdx.x;
    const int tid = threadIdx.x, lane = tid & 31, w = tid >> 5;

    const float* cbase = ctx + ((size_t)b * LL + (size_t)sp * LC) * DH;

    auto pf = [&](int p, int s) {
        const float* src = cbase + (size_t)(16 * p + 2 * w) * DH + lane * 4;
        float* dst = ring + (size_t)((w * 2 + s) * 2) * 512 + lane * 4;
#pragma unroll
        for (int i = 0; i < 8; i++)
            __pipeline_memcpy_async(dst + i * 128, src + i * 128, 16);
    };

    // PDL prologue: context prefetch + sacc zero before g_target dependence
    pf(0, 0); __pipeline_commit();
    for (int i = tid; i < 2 * DH; i += 256) sacc[i] = 0.f;

    cudaGridDependencySynchronize();   // g_target now valid

    {   // sq[k][j][l][t] = target[b, (l+32j)*8 + 2t + k]
        int k = tid >> 7, j = (tid >> 5) & 3, l = tid & 31;
        const float* g = g_target + (size_t)b * DD + (size_t)(l + 32 * j) * 8 + k;
        float4 v; v.x = g[0]; v.y = g[2]; v.z = g[4]; v.w = g[6];
        *(float4*)&sqm[((k * 4 + j) * 32 + l) * 4] = v;
    }
    __syncthreads();

    float a0[16], a1[16];
#pragma unroll
    for (int i = 0; i < 16; i++) { a0[i] = 0.f; a1[i] = 0.f; }
    float m0 = -1e30f, m1 = -1e30f, s0 = 0.f, s1 = 0.f;

#pragma unroll
    for (int p = 0; p < NPAIR; p++) {
        const int st = p & 1;
        if (p + 1 < NPAIR) pf(p + 1, st ^ 1);
        __pipeline_commit();
        __pipeline_wait_prior(1);
        __syncwarp();

        const float* rA = ring + (size_t)((w * 2 + st) * 2) * 512;
        const float* rB = rA + 512;

        float dA0 = 0.f, dA1 = 0.f, dB0 = 0.f, dB1 = 0.f;
#pragma unroll
        for (int j = 0; j < 4; j++) {
            float4 q0v = *(const float4*)&sqm[((0 * 4 + j) * 32 + lane) * 4];
            float4 q1v = *(const float4*)&sqm[((1 * 4 + j) * 32 + lane) * 4];
            float4 va  = *(const float4*)&rA[(lane + 32 * j) * 4];
            float4 vb  = *(const float4*)&rB[(lane + 32 * j) * 4];
            dA0 = fmaf(va.x, q0v.x, dA0); dA0 = fmaf(va.y, q0v.y, dA0);
            dA0 = fmaf(va.z, q0v.z, dA0); dA0 = fmaf(va.w, q0v.w, dA0);
            dA1 = fmaf(va.x, q1v.x, dA1); dA1 = fmaf(va.y, q1v.y, dA1);
            dA1 = fmaf(va.z, q1v.z, dA1); dA1 = fmaf(va.w, q1v.w, dA1);
            dB0 = fmaf(vb.x, q0v.x, dB0); dB0 = fmaf(vb.y, q0v.y, dB0);
            dB0 = fmaf(vb.z, q0v.z, dB0); dB0 = fmaf(vb.w, q0v.w, dB0);
            dB1 = fmaf(vb.x, q1v.x, dB1); dB1 = fmaf(vb.y, q1v.y, dB1);
            dB1 = fmaf(vb.z, q1v.z, dB1); dB1 = fmaf(vb.w, q1v.w, dB1);
        }
#pragma unroll
        for (int o = 16; o; o >>= 1) {
            dA0 += __shfl_xor_sync(0xffffffffu, dA0, o);
            dA1 += __shfl_xor_sync(0xffffffffu, dA1, o);
            dB0 += __shfl_xor_sync(0xffffffffu, dB0, o);
            dB1 += __shfl_xor_sync(0xffffffffu, dB1, o);
        }
        int r = 16 * p + 2 * w;
        if (lane == 0) {
            slog[0 * 128 + r] = dA0; slog[0 * 128 + r + 1] = dB0;
            slog[1 * 128 + r] = dA1; slog[1 * 128 + r + 1] = dB1;
        }
        float n0 = fmaxf(m0, fmaxf(dA0, dB0));
        float n1 = fmaxf(m1, fmaxf(dA1, dB1));
        float r0 = __expf(m0 - n0), r1 = __expf(m1 - n1);
        float eA0 = __expf(dA0 - n0), eB0 = __expf(dB0 - n0);
        float eA1 = __expf(dA1 - n1), eB1 = __expf(dB1 - n1);
        s0 = s0 * r0 + eA0 + eB0; m0 = n0;
        s1 = s1 * r1 + eA1 + eB1; m1 = n1;
        if (r0 != 1.f || r1 != 1.f) {
#pragma unroll
            for (int i = 0; i < 16; i++) { a0[i] *= r0; a1[i] *= r1; }
        }
#pragma unroll
        for (int j = 0; j < 4; j++) {
            float4 va = *(const float4*)&rA[(lane + 32 * j) * 4];
            float4 vb = *(const float4*)&rB[(lane + 32 * j) * 4];
            a0[4 * j + 0] = fmaf(eB0, vb.x, fmaf(eA0, va.x, a0[4 * j + 0]));
            a0[4 * j + 1] = fmaf(eB0, vb.y, fmaf(eA0, va.y, a0[4 * j + 1]));
            a0[4 * j + 2] = fmaf(eB0, vb.z, fmaf(eA0, va.z, a0[4 * j + 2]));
            a0[4 * j + 3] = fmaf(eB0, vb.w, fmaf(eA0, va.w, a0[4 * j + 3]));
            a1[4 * j + 0] = fmaf(eB1, vb.x, fmaf(eA1, va.x, a1[4 * j + 0]));
            a1[4 * j + 1] = fmaf(eB1, vb.y, fmaf(eA1, va.y, a1[4 * j + 1]));
            a1[4 * j + 2] = fmaf(eB1, vb.z, fmaf(eA1, va.z, a1[4 * j + 2]));
            a1[4 * j + 3] = fmaf(eB1, vb.w, fmaf(eA1, va.w, a1[4 * j + 3]));
        }
    }

    if (lane == 0) {
        smx[0 * 8 + w] = m0; smx[1 * 8 + w] = m1;
        ssm[0 * 8 + w] = s0; ssm[1 * 8 + w] = s1;
    }
    __syncthreads();

    {   // bulk coalesced store of raw logits (normalized in combine2)
        float* a0s = attn0 + (size_t)b * LL + sp * LC;
        float* a1s = attn1 + (size_t)b * LL + sp * LC;
        for (int i = tid; i < LC; i += 256) {
            a0s[i] = slog[0 * 128 + i];
            a1s[i] = slog[1 * 128 + i];
        }
    }

    float M0 = -1e30f, M1 = -1e30f;
#pragma unroll
    for (int ww = 0; ww < 8; ww++) {
        M0 = fmaxf(M0, smx[0 * 8 + ww]);
        M1 = fmaxf(M1, smx[1 * 8 + ww]);
    }
    float f0 = __expf(m0 - M0);
    float f1 = __expf(m1 - M1);
#pragma unroll
    for (int j = 0; j < 4; j++)
#pragma unroll
        for (int t = 0; t < 4; t++) {
            int d = (lane + 32 * j) * 4 + t;
            atomicAdd(&sacc[d],      a0[4 * j + t] * f0);
            atomicAdd(&sacc[DH + d], a1[4 * j + t] * f1);
        }
    __syncthreads();

    int idx0 = (b * 2 + 0) * SPLIT + sp;
    int idx1 = (b * 2 + 1) * SPLIT + sp;
    if (tid == 0) {
        float S0 = 0.f, S1 = 0.f;
#pragma unroll
        for (int ww = 0; ww < 8; ww++) {
            S0 += ssm[0 * 8 + ww] * __expf(smx[0 * 8 + ww] - M0);
            S1 += ssm[1 * 8 + ww] * __expf(smx[1 * 8 + ww] - M1);
        }
        g_pm[idx0] = M0; g_ps[idx0] = S0;
        g_pm[idx1] = M1; g_ps[idx1] = S1;
    }
    for (int i = tid; i < DH; i += 256) {
        g_pacc[(size_t)idx0 * DH + i] = sacc[i];
        g_pacc[(size_t)idx1 * DH + i] = sacc[DH + i];
    }
}

// ---------------- idx 3: combine + normalize logits (PDL top-sync) ----------
__global__ __launch_bounds__(256) void combine2(float* __restrict__ out) {
    cudaGridDependencySynchronize();   // g_pm/g_ps/g_pacc + raw logits from attn
    int bk = blockIdx.x >> 1;
    int half = blockIdx.x & 1;
    int d  = half * 256 + threadIdx.x;

    float pm[SPLIT], wv[SPLIT];
#pragma unroll
    for (int i = 0; i < SPLIT; i++) pm[i] = g_pm[bk * SPLIT + i];
    float M = pm[0];
#pragma unroll
    for (int i = 1; i < SPLIT; i++) M = fmaxf(M, pm[i]);
    float S = 0.f;
#pragma unroll
    for (int i = 0; i < SPLIT; i++) {
        wv[i] = __expf(pm[i] - M);
        S += g_ps[bk * SPLIT + i] * wv[i];
    }
    float inv = 1.0f / S;

    const float* pa = g_pacc + (size_t)bk * SPLIT * DH + d;
    float acc = 0.f;
#pragma unroll
    for (int i = 0; i < SPLIT; i++) acc += pa[(size_t)i * DH] * wv[i];
    int b = bk >> 1, k = bk & 1;
    g_wctx[(size_t)b * DD + k * DH + d] = acc * inv;

    // normalize this (b,k)'s logits: 1024 contiguous floats per CTA
    float* ap = out + BB * DD + (size_t)k * BB * LL + (size_t)b * LL
              + half * 1024 + threadIdx.x * 4;
    float4 v = *(float4*)ap;
    v.x = __expf(v.x - M) * inv;
    v.y = __expf(v.y - M) * inv;
    v.z = __expf(v.z - M) * inv;
    v.w = __expf(v.w - M) * inv;
    *(float4*)ap = v;
}

// ---------------- idx 4: pure output GEMM + tanh ticket (PDL top-sync) ------
__global__ __launch_bounds__(256) void final_k(const float* __restrict__ Wout,
                                               float* __restrict__ out) {
    cudaGridDependencySynchronize();   // g_wctx from combine2
    int tile = blockIdx.x >> 3, split = blockIdx.x & 7;
    gemm_body(g_wctx, DD, Wout, 2 * DD, g_acc5, DD / 8,
              tile * 64, split * (DD / 8), false);
    __threadfence();
    __shared__ unsigned s_old;
    __syncthreads();
    if (threadIdx.x == 0) s_old = atomicAdd(&g_tile_ctr[tile], 1u);
    __syncthreads();
    if (s_old == 7u) {
        __threadfence();
        int n0 = tile * 64;
        for (int i = threadIdx.x; i < 64 * 64; i += 256) {
            int r = i >> 6, c = i & 63;
            out[(size_t)r * DD + n0 + c] = tanhf(g_acc5[(size_t)r * DD + n0 + c]);
        }
    }
}

// ---------------- PDL launch helper ----------------
template <typename F, typename... Args>
static inline void launch_pdl(F kern, dim3 grid, dim3 block, size_t shm, Args... args) {
    cudaLaunchConfig_t cfg = {};
    cfg.gridDim = grid; cfg.blockDim = block;
    cfg.dynamicSmemBytes = shm; cfg.stream = 0;
    cudaLaunchAttribute attr[1];
    attr[0].id = cudaLaunchAttributeProgrammaticStreamSerialization;
    attr[0].val.programmaticStreamSerializationAllowed = 1;
    cfg.attrs = attr; cfg.numAttrs = 1;
    cudaLaunchKernelEx(&cfg, kern, args...);
}

// ---------------- launcher: 5 kernels, all PDL-chained ----------------
extern "C" void kernel_launch(void* const* d_in, const int* in_sizes, int n_in,
                              void* d_out, int out_size) {
    const float* input   = (const float*)d_in[0]; // [64,1024]
    const float* context = (const float*)d_in[1]; // [64,2048,512]
    const float* W_in    = (const float*)d_in[2]; // [1024,1024]
    const float* W_out   = (const float*)d_in[3]; // [1024,2048]
    float* out = (float*)d_out;                   // [ctxOut | attn0 | attn1]
    float* attn0 = out + BB * DD;
    float* attn1 = attn0 + BB * LL;

    static int inited = 0;
    if (!inited) {
        cudaFuncSetAttribute(attn_pass, cudaFuncAttributeMaxDynamicSharedMemorySize, SMEM_BYTES);
        inited = 1;
    }

    launch_pdl(prep_kernel, dim3(256), dim3(256), 0);
    launch_pdl(gemm_dual, dim3(16, 8, 2), dim3(256), 0, input, W_in, W_out);
    launch_pdl(attn_pass, dim3(SPLIT, BB), dim3(256), (size_t)SMEM_BYTES,
               (const float*)context, attn0, attn1);
    launch_pdl(combine2, dim3(256), dim3(256), 0, out);
    launch_pdl(final_k, dim3(128), dim3(256), 0, (const float*)W_out, out);
}